// round 3
// baseline (speedup 1.0000x reference)
#include <cuda_runtime.h>
#include <cuda_fp16.h>
#include <cstdint>

#define MDIM 2048
#define NDIM 8192
#define KDIM 8192

// Scratch (__device__ globals; allocation-free rules)
__device__ __align__(256) __half g_Xh[(size_t)MDIM * KDIM];   // A [M][K] K-major, 32 MiB
__device__ __align__(256) __half g_Wh[(size_t)NDIM * KDIM];   // B [N][K] K-major, 128 MiB

// ---------------- Cl(4,1) sign ----------------
__device__ __forceinline__ float gp_sign(int a, int b) {
    int swaps = 0;
    int t = a >> 1;
    while (t) { swaps += __popc(t & b); t >>= 1; }
    float s = (swaps & 1) ? -1.0f : 1.0f;
    if ((a & b) & 16) s = -s;
    return s;
}

// ---------------- Prep: x->fp16  AND  weight->expanded B[N][K] fp16 ----------------
// blocks [0,16384): convert x.  blocks [16384,24576): expand weight.
__global__ void prep_kernel(const float4* __restrict__ x, const float* __restrict__ w) {
    if (blockIdx.x < 16384) {
        size_t i = (size_t)blockIdx.x * 256 + threadIdx.x;   // < 4,194,304
        float4 v = x[i];
        __half2* xh = reinterpret_cast<__half2*>(g_Xh);
        xh[2 * i]     = __floats2half2_rn(v.x, v.y);
        xh[2 * i + 1] = __floats2half2_rn(v.z, v.w);
    } else {
        int idx = (blockIdx.x - 16384) * 256 + threadIdx.x;  // < 2,097,152
        int i  = idx & 255;
        int kb = (idx >> 8) & 31;
        int o  = idx >> 13;
        // B[(o*32+kb)][(i*32+l)] = weight[o,i,l^kb] * gp_sign(l^kb, l)
        const float4* wrow = reinterpret_cast<const float4*>(w + (size_t)(o * 256 + i) * 32);
        float wreg[32];
#pragma unroll
        for (int q = 0; q < 8; q++) {
            float4 v = wrow[q];
            wreg[4 * q] = v.x; wreg[4 * q + 1] = v.y;
            wreg[4 * q + 2] = v.z; wreg[4 * q + 3] = v.w;
        }
        __half tmp[32];
#pragma unroll
        for (int l = 0; l < 32; l++) {
            int j = l ^ kb;
            tmp[l] = __float2half_rn(wreg[j] * gp_sign(j, l));
        }
        uint4* dst = reinterpret_cast<uint4*>(g_Wh + (size_t)(o * 32 + kb) * KDIM + i * 32);
        const uint4* src = reinterpret_cast<const uint4*>(tmp);
        dst[0] = src[0]; dst[1] = src[1]; dst[2] = src[2]; dst[3] = src[3];
    }
}

// ---------------- GEMM: C[M,N] = A[M,K] * B[N,K]^T, fp16 in / fp32 acc ----------------
// CTA 128(M) x 256(N), BK=64, 3-stage cp.async, 8 warps (2M x 4N), warp tile 64x64.
#define BM 128
#define BN 256
#define BK 64
#define LDS 72                     // 64 + 8 halves pad (144B rows: conflict-free ldmatrix)
#define STAGES 3
#define NT (KDIM / BK)             // 128
#define A_STAGE (BM * LDS)         // halves
#define B_STAGE (BN * LDS)
#define STAGE_HALVES (A_STAGE + B_STAGE)
#define SMEM_BYTES (STAGES * STAGE_HALVES * 2)   // 165,888 B

static __device__ __forceinline__ uint32_t smem_u32(const void* p) {
    return (uint32_t)__cvta_generic_to_shared(p);
}
static __device__ __forceinline__ void cp_async16(uint32_t s, const void* g) {
    asm volatile("cp.async.cg.shared.global [%0], [%1], 16;\n" :: "r"(s), "l"(g));
}

__global__ void __launch_bounds__(256, 1) gemm_hmma_kernel(float* __restrict__ C) {
    extern __shared__ __half sm[];

    const int tid  = threadIdx.x;
    const int lane = tid & 31;
    const int warp = tid >> 5;
    const int wm = (warp & 1) * 64;      // 2 warps along M
    const int wn = (warp >> 1) * 64;     // 4 warps along N
    const int bm = blockIdx.x * BM;
    const int bn = blockIdx.y * BN;

    const __half* A = g_Xh;
    const __half* B = g_Wh;

    float acc[4][8][4];
#pragma unroll
    for (int a = 0; a < 4; a++)
#pragma unroll
        for (int b = 0; b < 8; b++)
#pragma unroll
            for (int c = 0; c < 4; c++) acc[a][b][c] = 0.0f;

    auto load_stage = [&](int t) {
        const int s = t % STAGES;
        __half* sA = sm + s * STAGE_HALVES;
        __half* sB = sA + A_STAGE;
        const int k0 = t * BK;
        // A: 128 rows x 128B = 1024 x 16B chunks
#pragma unroll
        for (int q = 0; q < 4; q++) {
            int c = tid + q * 256;
            int r = c >> 3, cc = c & 7;
            cp_async16(smem_u32(sA + r * LDS + cc * 8),
                       A + (size_t)(bm + r) * KDIM + k0 + cc * 8);
        }
        // B: 256 rows x 128B = 2048 x 16B chunks
#pragma unroll
        for (int q = 0; q < 8; q++) {
            int c = tid + q * 256;
            int r = c >> 3, cc = c & 7;
            cp_async16(smem_u32(sB + r * LDS + cc * 8),
                       B + (size_t)(bn + r) * KDIM + k0 + cc * 8);
        }
        asm volatile("cp.async.commit_group;\n");
    };

    // Prologue: stages 0,1 in flight
    load_stage(0);
    load_stage(1);

    // Per-warp ldmatrix base addresses (byte offsets within a stage)
    // A fragment (row-major): lanes 0-15 rows, lanes>>4 selects k-half
    const uint32_t aOff = (uint32_t)(((wm + (lane & 15)) * LDS + (lane >> 4) * 8) * 2);
    // B fragment (n-rows, k-cols, non-trans): row = wn + (lane&7) + ((lane&16)>>1), col-half = (lane>>3)&1
    const uint32_t bOff = (uint32_t)(((wn + (lane & 7) + ((lane & 16) >> 1)) * LDS +
                                      ((lane >> 3) & 1) * 8) * 2);

    for (int t = 0; t < NT; t++) {
        if (t == NT - 1) asm volatile("cp.async.wait_group 0;\n");
        else             asm volatile("cp.async.wait_group 1;\n");
        __syncthreads();

        if (t + 2 < NT) load_stage(t + 2);

        const int s = t % STAGES;
        const uint32_t aBase = smem_u32(sm + s * STAGE_HALVES) + aOff;
        const uint32_t bBase = smem_u32(sm + s * STAGE_HALVES + A_STAGE) + bOff;

#pragma unroll
        for (int ks = 0; ks < 4; ks++) {
            uint32_t a[4][4];
#pragma unroll
            for (int mi = 0; mi < 4; mi++) {
                uint32_t addr = aBase + (mi * 16 * LDS + ks * 16) * 2;
                asm volatile("ldmatrix.sync.aligned.m8n8.x4.shared.b16 {%0,%1,%2,%3}, [%4];\n"
                             : "=r"(a[mi][0]), "=r"(a[mi][1]), "=r"(a[mi][2]), "=r"(a[mi][3])
                             : "r"(addr));
            }
            uint32_t b[8][2];
#pragma unroll
            for (int nb = 0; nb < 4; nb++) {
                uint32_t addr = bBase + (nb * 16 * LDS + ks * 16) * 2;
                asm volatile("ldmatrix.sync.aligned.m8n8.x4.shared.b16 {%0,%1,%2,%3}, [%4];\n"
                             : "=r"(b[2 * nb][0]), "=r"(b[2 * nb][1]),
                               "=r"(b[2 * nb + 1][0]), "=r"(b[2 * nb + 1][1])
                             : "r"(addr));
            }
#pragma unroll
            for (int mi = 0; mi < 4; mi++)
#pragma unroll
                for (int nj = 0; nj < 8; nj++) {
                    asm volatile(
                        "mma.sync.aligned.m16n8k16.row.col.f32.f16.f16.f32 "
                        "{%0,%1,%2,%3},{%4,%5,%6,%7},{%8,%9},{%0,%1,%2,%3};\n"
                        : "+f"(acc[mi][nj][0]), "+f"(acc[mi][nj][1]),
                          "+f"(acc[mi][nj][2]), "+f"(acc[mi][nj][3])
                        : "r"(a[mi][0]), "r"(a[mi][1]), "r"(a[mi][2]), "r"(a[mi][3]),
                          "r"(b[nj][0]), "r"(b[nj][1]));
                }
        }
        __syncthreads();
    }

    // ---------------- fused normalize + store ----------------
    // Warp covers 64 cols = 2 o-groups of 32. Thread holds cols (lane&3)*2+{0,1} in each n8.
    // Sum-of-squares per row over a 32-col group: local 8 vals + quad shuffle (xor 1,2).
#pragma unroll
    for (int mi = 0; mi < 4; mi++) {
        const int r0 = bm + wm + mi * 16 + (lane >> 2);
#pragma unroll
        for (int g = 0; g < 2; g++) {          // o-group within warp tile
#pragma unroll
            for (int h = 0; h < 2; h++) {      // row-half: r0 (+0) and r0+8
                float ss = 0.0f;
#pragma unroll
                for (int q = 0; q < 4; q++) {
                    int nj = g * 4 + q;
                    ss += acc[mi][nj][2 * h] * acc[mi][nj][2 * h] +
                          acc[mi][nj][2 * h + 1] * acc[mi][nj][2 * h + 1];
                }
                ss += __shfl_xor_sync(0xffffffffu, ss, 1);
                ss += __shfl_xor_sync(0xffffffffu, ss, 2);
                const float sc = rsqrtf(ss + 1e-6f);
                float* row = C + (size_t)(r0 + h * 8) * NDIM + bn + wn + g * 32 + (lane & 3) * 2;
#pragma unroll
                for (int q = 0; q < 4; q++) {
                    int nj = g * 4 + q;
                    *reinterpret_cast<float2*>(row + q * 8) =
                        make_float2(acc[mi][nj][2 * h] * sc, acc[mi][nj][2 * h + 1] * sc);
                }
            }
        }
    }
}

// ---------------- launch ----------------
extern "C" void kernel_launch(void* const* d_in, const int* in_sizes, int n_in,
                              void* d_out, int out_size) {
    const float* x = (const float*)d_in[0];   // [2,1024,256,32] fp32
    const float* w = (const float*)d_in[1];   // [256,256,32]   fp32
    float* out = (float*)d_out;               // [2,1024,256,32] fp32

    prep_kernel<<<24576, 256>>>((const float4*)x, w);

    cudaFuncSetAttribute(gemm_hmma_kernel,
                         cudaFuncAttributeMaxDynamicSharedMemorySize, SMEM_BYTES);
    dim3 grid(MDIM / BM, NDIM / BN);   // (16, 32), m-fast
    gemm_hmma_kernel<<<grid, 256, SMEM_BYTES>>>(out);
}

// round 4
// speedup vs baseline: 1.1381x; 1.1381x over previous
#include <cuda_runtime.h>
#include <cuda_fp16.h>
#include <cstdint>

#define MDIM 2048
#define NDIM 8192
#define KDIM 8192

// Scratch (__device__ globals; allocation-free rules)
__device__ __align__(256) __half g_Xh[(size_t)MDIM * KDIM];   // A [M][K] K-major, 32 MiB
__device__ __align__(256) __half g_Wh[(size_t)NDIM * KDIM];   // B [N][K] K-major, 128 MiB

// ---------------- Cl(4,1) sign ----------------
__device__ __forceinline__ float gp_sign(int a, int b) {
    int swaps = 0;
    int t = a >> 1;
    while (t) { swaps += __popc(t & b); t >>= 1; }
    float s = (swaps & 1) ? -1.0f : 1.0f;
    if ((a & b) & 16) s = -s;
    return s;
}

// ---------------- Prep: x->fp16  AND  weight->expanded B[N][K] fp16 ----------------
__global__ void prep_kernel(const float4* __restrict__ x, const float* __restrict__ w) {
    if (blockIdx.x < 16384) {
        size_t i = (size_t)blockIdx.x * 256 + threadIdx.x;
        float4 v = x[i];
        __half2* xh = reinterpret_cast<__half2*>(g_Xh);
        xh[2 * i]     = __floats2half2_rn(v.x, v.y);
        xh[2 * i + 1] = __floats2half2_rn(v.z, v.w);
    } else {
        int idx = (blockIdx.x - 16384) * 256 + threadIdx.x;
        int i  = idx & 255;
        int kb = (idx >> 8) & 31;
        int o  = idx >> 13;
        const float4* wrow = reinterpret_cast<const float4*>(w + (size_t)(o * 256 + i) * 32);
        float wreg[32];
#pragma unroll
        for (int q = 0; q < 8; q++) {
            float4 v = wrow[q];
            wreg[4 * q] = v.x; wreg[4 * q + 1] = v.y;
            wreg[4 * q + 2] = v.z; wreg[4 * q + 3] = v.w;
        }
        __half tmp[32];
#pragma unroll
        for (int l = 0; l < 32; l++) {
            int j = l ^ kb;
            tmp[l] = __float2half_rn(wreg[j] * gp_sign(j, l));
        }
        uint4* dst = reinterpret_cast<uint4*>(g_Wh + (size_t)(o * 32 + kb) * KDIM + i * 32);
        const uint4* src = reinterpret_cast<const uint4*>(tmp);
        dst[0] = src[0]; dst[1] = src[1]; dst[2] = src[2]; dst[3] = src[3];
    }
}

// ---------------- GEMM: C = A * B^T, fp16 in / fp32 acc ----------------
// CTA 128(M) x 256(N), BK=64, 3-stage, 512 threads = 16 warps (2M x 8N), warp 64x32.
// Smem rows: 64 halves = 128B = 8 chunks of 16B, XOR swizzle chunk^(row&7).
#define BM 128
#define BN 256
#define BK 64
#define STAGES 3
#define NT (KDIM / BK)             // 128
#define A_BYTES (BM * 128)         // 16384
#define B_BYTES (BN * 128)         // 32768
#define STAGE_BYTES (A_BYTES + B_BYTES)          // 49152
#define SMEM_BYTES (STAGES * STAGE_BYTES)        // 147456

static __device__ __forceinline__ uint32_t smem_u32(const void* p) {
    return (uint32_t)__cvta_generic_to_shared(p);
}
static __device__ __forceinline__ void cp_async16(uint32_t s, const void* g) {
    asm volatile("cp.async.cg.shared.global [%0], [%1], 16;\n" :: "r"(s), "l"(g));
}

__global__ void __launch_bounds__(512, 1) gemm_hmma_kernel(float* __restrict__ C) {
    extern __shared__ char sm[];
    const uint32_t sbase = smem_u32(sm);

    const int tid  = threadIdx.x;
    const int lane = tid & 31;
    const int warp = tid >> 5;
    const int wm = (warp & 1) * 64;      // 2 warps along M
    const int wn = (warp >> 1) * 32;     // 8 warps along N
    const int bm = blockIdx.x * BM;
    const int bn = blockIdx.y * BN;

    const __half* A = g_Xh;
    const __half* B = g_Wh;

    float acc[4][4][4];
#pragma unroll
    for (int a = 0; a < 4; a++)
#pragma unroll
        for (int b = 0; b < 4; b++)
#pragma unroll
            for (int c = 0; c < 4; c++) acc[a][b][c] = 0.0f;

    auto load_stage = [&](int t) {
        const uint32_t st = sbase + (t % STAGES) * STAGE_BYTES;
        const int k0 = t * BK;
        // A: 128 rows x 8 chunks = 1024 chunks, 512 threads x 2
#pragma unroll
        for (int q = 0; q < 2; q++) {
            int c = tid + q * 512;
            int r = c >> 3, cc = c & 7;
            cp_async16(st + r * 128 + ((cc ^ (r & 7)) * 16),
                       A + (size_t)(bm + r) * KDIM + k0 + cc * 8);
        }
        // B: 256 rows x 8 chunks = 2048 chunks, 512 threads x 4
#pragma unroll
        for (int q = 0; q < 4; q++) {
            int c = tid + q * 512;
            int r = c >> 3, cc = c & 7;
            cp_async16(st + A_BYTES + r * 128 + ((cc ^ (r & 7)) * 16),
                       B + (size_t)(bn + r) * KDIM + k0 + cc * 8);
        }
        asm volatile("cp.async.commit_group;\n");
    };

    load_stage(0);
    load_stage(1);

    // Lane-constant fragment addressing (swizzle row-xor is mi/nb-invariant: 16 ≡ 0 mod 8)
    const int aRow = wm + (lane & 15);
    const int aHi  = lane >> 4;            // k-half chunk
    const int aRx  = aRow & 7;
    const int bRow = wn + (lane & 7) + ((lane & 16) >> 1);
    const int bHi  = (lane >> 3) & 1;
    const int bRx  = bRow & 7;

    for (int t = 0; t < NT; t++) {
        if (t == NT - 1) asm volatile("cp.async.wait_group 0;\n");
        else             asm volatile("cp.async.wait_group 1;\n");
        __syncthreads();

        if (t + 2 < NT) load_stage(t + 2);

        const uint32_t st = sbase + (t % STAGES) * STAGE_BYTES;
        const uint32_t aB = st + aRow * 128;
        const uint32_t bB = st + A_BYTES + bRow * 128;

#pragma unroll
        for (int ks = 0; ks < 4; ks++) {
            uint32_t a[4][4];
#pragma unroll
            for (int mi = 0; mi < 4; mi++) {
                uint32_t addr = aB + mi * (16 * 128) + (((ks * 2 + aHi) ^ aRx) * 16);
                asm volatile("ldmatrix.sync.aligned.m8n8.x4.shared.b16 {%0,%1,%2,%3}, [%4];\n"
                             : "=r"(a[mi][0]), "=r"(a[mi][1]), "=r"(a[mi][2]), "=r"(a[mi][3])
                             : "r"(addr));
            }
            uint32_t b[4][2];
#pragma unroll
            for (int nb = 0; nb < 2; nb++) {
                uint32_t addr = bB + nb * (16 * 128) + (((ks * 2 + bHi) ^ bRx) * 16);
                asm volatile("ldmatrix.sync.aligned.m8n8.x4.shared.b16 {%0,%1,%2,%3}, [%4];\n"
                             : "=r"(b[2 * nb][0]), "=r"(b[2 * nb][1]),
                               "=r"(b[2 * nb + 1][0]), "=r"(b[2 * nb + 1][1])
                             : "r"(addr));
            }
#pragma unroll
            for (int mi = 0; mi < 4; mi++)
#pragma unroll
                for (int nj = 0; nj < 4; nj++) {
                    asm volatile(
                        "mma.sync.aligned.m16n8k16.row.col.f32.f16.f16.f32 "
                        "{%0,%1,%2,%3},{%4,%5,%6,%7},{%8,%9},{%0,%1,%2,%3};\n"
                        : "+f"(acc[mi][nj][0]), "+f"(acc[mi][nj][1]),
                          "+f"(acc[mi][nj][2]), "+f"(acc[mi][nj][3])
                        : "r"(a[mi][0]), "r"(a[mi][1]), "r"(a[mi][2]), "r"(a[mi][3]),
                          "r"(b[nj][0]), "r"(b[nj][1]));
                }
        }
    }

    // ---------------- fused normalize + store ----------------
    // Warp tile 64x32: the 32 N-cols are exactly one o-group (one multivector per row).
#pragma unroll
    for (int mi = 0; mi < 4; mi++) {
        const int r0 = bm + wm + mi * 16 + (lane >> 2);
#pragma unroll
        for (int h = 0; h < 2; h++) {
            float ss = 0.0f;
#pragma unroll
            for (int nj = 0; nj < 4; nj++)
                ss += acc[mi][nj][2 * h] * acc[mi][nj][2 * h] +
                      acc[mi][nj][2 * h + 1] * acc[mi][nj][2 * h + 1];
            ss += __shfl_xor_sync(0xffffffffu, ss, 1);
            ss += __shfl_xor_sync(0xffffffffu, ss, 2);
            const float sc = rsqrtf(ss + 1e-6f);
            float* row = C + (size_t)(r0 + h * 8) * NDIM + bn + wn + (lane & 3) * 2;
#pragma unroll
            for (int nj = 0; nj < 4; nj++)
                *reinterpret_cast<float2*>(row + nj * 8) =
                    make_float2(acc[mi][nj][2 * h] * sc, acc[mi][nj][2 * h + 1] * sc);
        }
    }
}

// ---------------- launch ----------------
extern "C" void kernel_launch(void* const* d_in, const int* in_sizes, int n_in,
                              void* d_out, int out_size) {
    const float* x = (const float*)d_in[0];   // [2,1024,256,32] fp32
    const float* w = (const float*)d_in[1];   // [256,256,32]   fp32
    float* out = (float*)d_out;               // [2,1024,256,32] fp32

    prep_kernel<<<24576, 256>>>((const float4*)x, w);

    cudaFuncSetAttribute(gemm_hmma_kernel,
                         cudaFuncAttributeMaxDynamicSharedMemorySize, SMEM_BYTES);
    dim3 grid(MDIM / BM, NDIM / BN);   // (16, 32), m-fast
    gemm_hmma_kernel<<<grid, 512, SMEM_BYTES>>>(out);
}

// round 5
// speedup vs baseline: 2.3004x; 2.0212x over previous
#include <cuda_runtime.h>
#include <cuda_fp16.h>
#include <cstdint>

// Logical GEMM dims in the matrix representation:
#define M2 8192    // (b*s)*4 matrix columns c
#define N2 2048    // o*8: (r, pn)
#define K2 2048    // i*8: (q, pk)

// Scratch (__device__ globals; allocation-free rules)
__device__ __align__(256) __half g_A[(size_t)M2 * K2];   // 32 MiB
__device__ __align__(256) __half g_B[(size_t)N2 * K2];   // 8 MiB
__device__ __align__(256) float  g_O[(size_t)M2 * N2];   // 64 MiB

// Representation matrices and derived tables
__device__ float g_Rre[32][4][4], g_Rim[32][4][4];
__device__ int   g_xEncA[32][8];  __device__ float g_xEncC[32][8];
__device__ int   g_wEncA[64][8];  __device__ float g_wEncC[64][8];
__device__ int   g_decU[32][4];   __device__ float g_decRe[32][4], g_decIm[32][4];

// ---------------- complex 4x4 matmul ----------------
__device__ void cmul4(const float Ar[4][4], const float Ai[4][4],
                      const float Br[4][4], const float Bi[4][4],
                      float Cr[4][4], float Ci[4][4]) {
    for (int i = 0; i < 4; i++)
        for (int j = 0; j < 4; j++) {
            float re = 0.f, im = 0.f;
            for (int k = 0; k < 4; k++) {
                re += Ar[i][k] * Br[k][j] - Ai[i][k] * Bi[k][j];
                im += Ar[i][k] * Bi[k][j] + Ai[i][k] * Br[k][j];
            }
            Cr[i][j] = re; Ci[i][j] = im;
        }
}

// ---------------- setup: build R_a and tables (32 threads) ----------------
__global__ void setup_kernel() {
    const int a = threadIdx.x;   // 0..31
    float Gre[5][4][4] = {}, Gim[5][4][4] = {};
    // gamma1 = [[0,s1],[s1,0]]
    Gre[0][0][3] = 1; Gre[0][1][2] = 1; Gre[0][2][1] = 1; Gre[0][3][0] = 1;
    // gamma2 = [[0,s2],[s2,0]], s2 = [[0,-i],[i,0]]
    Gim[1][0][3] = -1; Gim[1][1][2] = 1; Gim[1][2][1] = -1; Gim[1][3][0] = 1;
    // gamma3 = [[0,s3],[s3,0]], s3 = [[1,0],[0,-1]]
    Gre[2][0][2] = 1; Gre[2][1][3] = -1; Gre[2][2][0] = 1; Gre[2][3][1] = -1;
    // gamma4 = [[I,0],[0,-I]]
    Gre[3][0][0] = 1; Gre[3][1][1] = 1; Gre[3][2][2] = -1; Gre[3][3][3] = -1;
    // G5 = i * g1*g2*g3*g4   (squares to -1, anticommutes with g1..g4)
    {
        float Tr[4][4], Ti[4][4], Ur[4][4], Ui[4][4], Vr[4][4], Vi[4][4];
        cmul4(Gre[0], Gim[0], Gre[1], Gim[1], Tr, Ti);
        cmul4(Tr, Ti, Gre[2], Gim[2], Ur, Ui);
        cmul4(Ur, Ui, Gre[3], Gim[3], Vr, Vi);
        for (int i = 0; i < 4; i++)
            for (int j = 0; j < 4; j++) { Gre[4][i][j] = -Vi[i][j]; Gim[4][i][j] = Vr[i][j]; }
    }
    // R_a = ascending product of generators in bitmask a
    float Rr[4][4] = {}, Ri[4][4] = {};
    Rr[0][0] = Rr[1][1] = Rr[2][2] = Rr[3][3] = 1.f;
    for (int b = 0; b < 5; b++)
        if ((a >> b) & 1) {
            float Tr[4][4], Ti[4][4];
            cmul4(Rr, Ri, Gre[b], Gim[b], Tr, Ti);
            for (int i = 0; i < 4; i++)
                for (int j = 0; j < 4; j++) { Rr[i][j] = Tr[i][j]; Ri[i][j] = Ti[i][j]; }
        }
    for (int i = 0; i < 4; i++)
        for (int j = 0; j < 4; j++) { g_Rre[a][i][j] = Rr[i][j]; g_Rim[a][i][j] = Ri[i][j]; }
    __syncthreads();

    if (a == 0) {
        // X-encode: u = c*8 + q*2 + pk ; coef over blades with R[q][c] != 0
        for (int u = 0; u < 32; u++) {
            int c = u >> 3, q = (u >> 1) & 3, pk = u & 1, e = 0;
            for (int t = 0; t < 8; t++) { g_xEncA[u][t] = 0; g_xEncC[u][t] = 0.f; }
            for (int bl = 0; bl < 32; bl++) {
                float re = g_Rre[bl][q][c], im = g_Rim[bl][q][c];
                if (fabsf(re) + fabsf(im) > 0.5f) {
                    g_xEncA[u][e] = bl;
                    g_xEncC[u][e] = pk ? im : re;
                    e++;
                }
            }
        }
        // W-encode: u = (r*2+pn)*8 + q*2 + pk
        for (int u = 0; u < 64; u++) {
            int rw = u >> 3, r = rw >> 1, pn = rw & 1;
            int qk = u & 7, q = qk >> 1, pk = qk & 1, e = 0;
            for (int t = 0; t < 8; t++) { g_wEncA[u][t] = 0; g_wEncC[u][t] = 0.f; }
            for (int bl = 0; bl < 32; bl++) {
                float re = g_Rre[bl][r][q], im = g_Rim[bl][r][q];
                if (fabsf(re) + fabsf(im) > 0.5f) {
                    float coef = (pn == 0) ? (pk == 0 ? re : -im)
                                           : (pk == 0 ? im : re);
                    g_wEncA[u][e] = bl;
                    g_wEncC[u][e] = coef;
                    e++;
                }
            }
        }
        // decode: x_a = 1/4 * sum_r [ReR[r][c]*OUTre + ImR[r][c]*OUTim], c = nonzero col
        for (int bl = 0; bl < 32; bl++)
            for (int r = 0; r < 4; r++)
                for (int c = 0; c < 4; c++) {
                    float re = g_Rre[bl][r][c], im = g_Rim[bl][r][c];
                    if (fabsf(re) + fabsf(im) > 0.5f) {
                        g_decU[bl][r]  = c * 8 + r * 2;
                        g_decRe[bl][r] = re * 0.25f;
                        g_decIm[bl][r] = im * 0.25f;
                    }
                }
    }
}

// ---------------- encode x: A[(bs*4+c)][(i*8+q*2+pk)] fp16 ----------------
// warp handles 32 consecutive multivectors (bs,i); lane = output component u.
__global__ void encode_x_kernel(const float* __restrict__ x) {
    const int lane = threadIdx.x & 31, warp = threadIdx.x >> 5;
    const int wg = blockIdx.x * 8 + warp;          // 0..16383
    const size_t mv0 = (size_t)wg * 32;
    int   ta[8]; float tc[8];
#pragma unroll
    for (int e = 0; e < 8; e++) { ta[e] = g_xEncA[lane][e]; tc[e] = g_xEncC[lane][e]; }
    const float* src = x + mv0 * 32;
    const int c = lane >> 3, qk = lane & 7;
#pragma unroll 4
    for (int j = 0; j < 32; j++) {
        float v = src[j * 32 + lane];              // blade 'lane' of mv j (coalesced)
        float o = 0.f;
#pragma unroll
        for (int e = 0; e < 8; e++)
            o += tc[e] * __shfl_sync(0xffffffffu, v, ta[e]);
        size_t mv = mv0 + j;
        size_t bs = mv >> 8, ii = mv & 255;
        g_A[(bs * 4 + c) * K2 + ii * 8 + qk] = __float2half_rn(o);
    }
}

// ---------------- encode w: B[(o*8+r*2+pn)][(i*8+q*2+pk)] fp16 ----------------
__global__ void encode_w_kernel(const float* __restrict__ w) {
    const int lane = threadIdx.x & 31, warp = threadIdx.x >> 5;
    const int wg = blockIdx.x * 8 + warp;          // 0..2047
    const int o = wg >> 3, i0 = (wg & 7) * 32;
    int   ta[2][8]; float tc[2][8];
#pragma unroll
    for (int p = 0; p < 2; p++)
#pragma unroll
        for (int e = 0; e < 8; e++) {
            ta[p][e] = g_wEncA[lane + 32 * p][e];
            tc[p][e] = g_wEncC[lane + 32 * p][e];
        }
#pragma unroll 2
    for (int j = 0; j < 32; j++) {
        int i = i0 + j;
        float v = w[((size_t)o * 256 + i) * 32 + lane];
#pragma unroll
        for (int p = 0; p < 2; p++) {
            int u = lane + 32 * p;
            float ov = 0.f;
#pragma unroll
            for (int e = 0; e < 8; e++)
                ov += tc[p][e] * __shfl_sync(0xffffffffu, v, ta[p][e]);
            g_B[(size_t)(o * 8 + (u >> 3)) * K2 + i * 8 + (u & 7)] = __float2half_rn(ov);
        }
    }
}

// ---------------- GEMM: g_O[M2][N2] = A * B^T, fp16 in / fp32 acc ----------------
#define BM 128
#define BN 256
#define BK 64
#define STAGES 3
#define NT (K2 / BK)               // 32
#define A_BYTES (BM * 128)
#define B_BYTES (BN * 128)
#define STAGE_BYTES (A_BYTES + B_BYTES)
#define SMEM_BYTES (STAGES * STAGE_BYTES)   // 147456

static __device__ __forceinline__ uint32_t smem_u32(const void* p) {
    return (uint32_t)__cvta_generic_to_shared(p);
}
static __device__ __forceinline__ void cp_async16(uint32_t s, const void* g) {
    asm volatile("cp.async.cg.shared.global [%0], [%1], 16;\n" :: "r"(s), "l"(g));
}

__global__ void __launch_bounds__(512, 1) gemm_hmma_kernel() {
    extern __shared__ char sm[];
    const uint32_t sbase = smem_u32(sm);

    const int tid  = threadIdx.x;
    const int lane = tid & 31;
    const int warp = tid >> 5;
    const int wm = (warp & 1) * 64;
    const int wn = (warp >> 1) * 32;
    const int bm = blockIdx.x * BM;
    const int bn = blockIdx.y * BN;

    const __half* A = g_A;
    const __half* B = g_B;

    float acc[4][4][4];
#pragma unroll
    for (int a = 0; a < 4; a++)
#pragma unroll
        for (int b = 0; b < 4; b++)
#pragma unroll
            for (int c = 0; c < 4; c++) acc[a][b][c] = 0.0f;

    auto load_stage = [&](int t) {
        const uint32_t st = sbase + (t % STAGES) * STAGE_BYTES;
        const int k0 = t * BK;
#pragma unroll
        for (int q = 0; q < 2; q++) {
            int c = tid + q * 512;
            int r = c >> 3, cc = c & 7;
            cp_async16(st + r * 128 + ((cc ^ (r & 7)) * 16),
                       A + (size_t)(bm + r) * K2 + k0 + cc * 8);
        }
#pragma unroll
        for (int q = 0; q < 4; q++) {
            int c = tid + q * 512;
            int r = c >> 3, cc = c & 7;
            cp_async16(st + A_BYTES + r * 128 + ((cc ^ (r & 7)) * 16),
                       B + (size_t)(bn + r) * K2 + k0 + cc * 8);
        }
        asm volatile("cp.async.commit_group;\n");
    };

    load_stage(0);
    load_stage(1);

    const int aRow = wm + (lane & 15);
    const int aHi  = lane >> 4;
    const int aRx  = aRow & 7;
    const int bRow = wn + (lane & 7) + ((lane & 16) >> 1);
    const int bHi  = (lane >> 3) & 1;
    const int bRx  = bRow & 7;

    for (int t = 0; t < NT; t++) {
        if (t == NT - 1) asm volatile("cp.async.wait_group 0;\n");
        else             asm volatile("cp.async.wait_group 1;\n");
        __syncthreads();

        if (t + 2 < NT) load_stage(t + 2);

        const uint32_t st = sbase + (t % STAGES) * STAGE_BYTES;
        const uint32_t aB = st + aRow * 128;
        const uint32_t bB = st + A_BYTES + bRow * 128;

#pragma unroll
        for (int ks = 0; ks < 4; ks++) {
            uint32_t a[4][4];
#pragma unroll
            for (int mi = 0; mi < 4; mi++) {
                uint32_t addr = aB + mi * (16 * 128) + (((ks * 2 + aHi) ^ aRx) * 16);
                asm volatile("ldmatrix.sync.aligned.m8n8.x4.shared.b16 {%0,%1,%2,%3}, [%4];\n"
                             : "=r"(a[mi][0]), "=r"(a[mi][1]), "=r"(a[mi][2]), "=r"(a[mi][3])
                             : "r"(addr));
            }
            uint32_t b[4][2];
#pragma unroll
            for (int nb = 0; nb < 2; nb++) {
                uint32_t addr = bB + nb * (16 * 128) + (((ks * 2 + bHi) ^ bRx) * 16);
                asm volatile("ldmatrix.sync.aligned.m8n8.x4.shared.b16 {%0,%1,%2,%3}, [%4];\n"
                             : "=r"(b[2 * nb][0]), "=r"(b[2 * nb][1]),
                               "=r"(b[2 * nb + 1][0]), "=r"(b[2 * nb + 1][1])
                             : "r"(addr));
            }
#pragma unroll
            for (int mi = 0; mi < 4; mi++)
#pragma unroll
                for (int nj = 0; nj < 4; nj++) {
                    asm volatile(
                        "mma.sync.aligned.m16n8k16.row.col.f32.f16.f16.f32 "
                        "{%0,%1,%2,%3},{%4,%5,%6,%7},{%8,%9},{%0,%1,%2,%3};\n"
                        : "+f"(acc[mi][nj][0]), "+f"(acc[mi][nj][1]),
                          "+f"(acc[mi][nj][2]), "+f"(acc[mi][nj][3])
                        : "r"(a[mi][0]), "r"(a[mi][1]), "r"(a[mi][2]), "r"(a[mi][3]),
                          "r"(b[nj][0]), "r"(b[nj][1]));
                }
        }
    }

    // plain fp32 store of raw accumulators
#pragma unroll
    for (int mi = 0; mi < 4; mi++) {
        const int r0 = bm + wm + mi * 16 + (lane >> 2);
#pragma unroll
        for (int h = 0; h < 2; h++) {
            float* row = g_O + (size_t)(r0 + h * 8) * N2 + bn + wn + (lane & 3) * 2;
#pragma unroll
            for (int nj = 0; nj < 4; nj++)
                *reinterpret_cast<float2*>(row + nj * 8) =
                    make_float2(acc[mi][nj][2 * h], acc[mi][nj][2 * h + 1]);
        }
    }
}

// ---------------- decode + normalize ----------------
// warp handles 16 multivectors (same bs); lane = blade a.
__global__ void decode_kernel(float* __restrict__ out) {
    const int lane = threadIdx.x & 31, warp = threadIdx.x >> 5;
    const int wg = blockIdx.x * 8 + warp;          // 0..32767
    const int mv0 = wg * 16;
    const int bs = mv0 >> 8, o0 = mv0 & 255;
    int tu[4]; float tre[4], tim[4];
#pragma unroll
    for (int r = 0; r < 4; r++) {
        tu[r]  = g_decU[lane][r];
        tre[r] = g_decRe[lane][r];
        tim[r] = g_decIm[lane][r];
    }
    const int c = lane >> 3, rp = lane & 7;
    const float* orow = g_O + (size_t)(bs * 4 + c) * N2;
#pragma unroll 2
    for (int j = 0; j < 16; j++) {
        const int o = o0 + j;
        float v = orow[o * 8 + rp];
        float xa = 0.f;
#pragma unroll
        for (int r = 0; r < 4; r++) {
            float vre = __shfl_sync(0xffffffffu, v, tu[r]);
            float vim = __shfl_sync(0xffffffffu, v, tu[r] + 1);
            xa += tre[r] * vre + tim[r] * vim;
        }
        float ss = xa * xa;
#pragma unroll
        for (int off = 16; off; off >>= 1) ss += __shfl_xor_sync(0xffffffffu, ss, off);
        out[((size_t)bs * 256 + o) * 32 + lane] = xa * rsqrtf(ss + 1e-6f);
    }
}

// ---------------- launch ----------------
extern "C" void kernel_launch(void* const* d_in, const int* in_sizes, int n_in,
                              void* d_out, int out_size) {
    const float* x = (const float*)d_in[0];   // [2,1024,256,32] fp32
    const float* w = (const float*)d_in[1];   // [256,256,32]   fp32
    float* out = (float*)d_out;               // [2,1024,256,32] fp32

    setup_kernel<<<1, 32>>>();
    encode_x_kernel<<<2048, 256>>>(x);
    encode_w_kernel<<<256, 256>>>(w);

    cudaFuncSetAttribute(gemm_hmma_kernel,
                         cudaFuncAttributeMaxDynamicSharedMemorySize, SMEM_BYTES);
    dim3 grid(M2 / BM, N2 / BN);   // (64, 8), m-fast
    gemm_hmma_kernel<<<grid, 512, SMEM_BYTES>>>();

    decode_kernel<<<4096, 256>>>(out);
}

// round 6
// speedup vs baseline: 3.5686x; 1.5513x over previous
#include <cuda_runtime.h>
#include <cuda_fp16.h>
#include <cstdint>

// Logical GEMM dims in the M4(C) matrix representation:
#define M2 8192    // (b*s)*4 matrix columns c
#define N2 2048    // o*8: (r, pn)
#define K2 2048    // i*8: (q, pk)

// Scratch (__device__ globals; allocation-free rules)
__device__ __align__(256) __half g_A[(size_t)M2 * K2];   // 32 MiB
__device__ __align__(256) __half g_B[(size_t)N2 * K2];   // 8 MiB

// ================= compile-time tables (Cl(4,1) ~= M4(C) rep) =================
struct Tables {
    int   xEncA[32][8]; float xEncC[32][8];
    int   wEncA[64][8]; float wEncC[64][8];
    int   decU[32][4];  float decRe[32][4]; float decIm[32][4];
};

constexpr float cfabs(float v) { return v < 0.f ? -v : v; }

constexpr void cmul4c(const float (&Ar)[4][4], const float (&Ai)[4][4],
                      const float (&Br)[4][4], const float (&Bi)[4][4],
                      float (&Cr)[4][4], float (&Ci)[4][4]) {
    for (int i = 0; i < 4; i++)
        for (int j = 0; j < 4; j++) {
            float re = 0.f, im = 0.f;
            for (int k = 0; k < 4; k++) {
                re += Ar[i][k] * Br[k][j] - Ai[i][k] * Bi[k][j];
                im += Ar[i][k] * Bi[k][j] + Ai[i][k] * Br[k][j];
            }
            Cr[i][j] = re; Ci[i][j] = im;
        }
}

constexpr Tables build_tables() {
    Tables T{};
    float Gre[5][4][4] = {}, Gim[5][4][4] = {};
    // gamma1 = [[0,s1],[s1,0]]
    Gre[0][0][3] = 1; Gre[0][1][2] = 1; Gre[0][2][1] = 1; Gre[0][3][0] = 1;
    // gamma2 = [[0,s2],[s2,0]], s2 = [[0,-i],[i,0]]
    Gim[1][0][3] = -1; Gim[1][1][2] = 1; Gim[1][2][1] = -1; Gim[1][3][0] = 1;
    // gamma3 = [[0,s3],[s3,0]], s3 = [[1,0],[0,-1]]
    Gre[2][0][2] = 1; Gre[2][1][3] = -1; Gre[2][2][0] = 1; Gre[2][3][1] = -1;
    // gamma4 = [[I,0],[0,-I]]
    Gre[3][0][0] = 1; Gre[3][1][1] = 1; Gre[3][2][2] = -1; Gre[3][3][3] = -1;
    // G5 = i * g1*g2*g3*g4  (squares to -1, anticommutes with g1..g4)
    {
        float Tr[4][4] = {}, Ti[4][4] = {}, Ur[4][4] = {}, Ui[4][4] = {};
        float Vr[4][4] = {}, Vi[4][4] = {};
        cmul4c(Gre[0], Gim[0], Gre[1], Gim[1], Tr, Ti);
        cmul4c(Tr, Ti, Gre[2], Gim[2], Ur, Ui);
        cmul4c(Ur, Ui, Gre[3], Gim[3], Vr, Vi);
        for (int i = 0; i < 4; i++)
            for (int j = 0; j < 4; j++) { Gre[4][i][j] = -Vi[i][j]; Gim[4][i][j] = Vr[i][j]; }
    }
    // R_a = ascending product of generators in bitmask a
    float Rre[32][4][4] = {}, Rim[32][4][4] = {};
    for (int a = 0; a < 32; a++) {
        float Rr[4][4] = {}, Ri[4][4] = {};
        Rr[0][0] = Rr[1][1] = Rr[2][2] = Rr[3][3] = 1.f;
        for (int b = 0; b < 5; b++)
            if ((a >> b) & 1) {
                float Tr[4][4] = {}, Ti[4][4] = {};
                cmul4c(Rr, Ri, Gre[b], Gim[b], Tr, Ti);
                for (int i = 0; i < 4; i++)
                    for (int j = 0; j < 4; j++) { Rr[i][j] = Tr[i][j]; Ri[i][j] = Ti[i][j]; }
            }
        for (int i = 0; i < 4; i++)
            for (int j = 0; j < 4; j++) { Rre[a][i][j] = Rr[i][j]; Rim[a][i][j] = Ri[i][j]; }
    }
    // X-encode: u = c*8 + q*2 + pk ; 8 blades with R[q][c] != 0
    for (int u = 0; u < 32; u++) {
        int c = u >> 3, q = (u >> 1) & 3, pk = u & 1, e = 0;
        for (int bl = 0; bl < 32; bl++) {
            float re = Rre[bl][q][c], im = Rim[bl][q][c];
            if (cfabs(re) + cfabs(im) > 0.5f) {
                T.xEncA[u][e] = bl;
                T.xEncC[u][e] = pk ? im : re;
                e++;
            }
        }
    }
    // W-encode: u = (r*2+pn)*8 + q*2 + pk
    for (int u = 0; u < 64; u++) {
        int rw = u >> 3, r = rw >> 1, pn = rw & 1;
        int qk = u & 7, q = qk >> 1, pk = qk & 1, e = 0;
        for (int bl = 0; bl < 32; bl++) {
            float re = Rre[bl][r][q], im = Rim[bl][r][q];
            if (cfabs(re) + cfabs(im) > 0.5f) {
                T.wEncA[u][e] = bl;
                T.wEncC[u][e] = (pn == 0) ? (pk == 0 ? re : -im)
                                          : (pk == 0 ? im : re);
                e++;
            }
        }
    }
    // decode: x_a = 1/4 * sum_r [ReR[r][c]*OUTre + ImR[r][c]*OUTim]
    for (int bl = 0; bl < 32; bl++)
        for (int r = 0; r < 4; r++)
            for (int c = 0; c < 4; c++) {
                float re = Rre[bl][r][c], im = Rim[bl][r][c];
                if (cfabs(re) + cfabs(im) > 0.5f) {
                    T.decU[bl][r]  = c * 8 + r * 2;
                    T.decRe[bl][r] = re * 0.25f;
                    T.decIm[bl][r] = im * 0.25f;
                }
            }
    return T;
}

__device__ const Tables c_T = build_tables();

// ---------------- encode x: A[(bs*4+c)][(i*8+q*2+pk)] fp16 ----------------
__global__ void encode_x_kernel(const float* __restrict__ x) {
    const int lane = threadIdx.x & 31, warp = threadIdx.x >> 5;
    const int wg = blockIdx.x * 8 + warp;          // 0..16383
    const size_t mv0 = (size_t)wg * 32;
    int ta[8]; float tc[8];
#pragma unroll
    for (int e = 0; e < 8; e++) { ta[e] = c_T.xEncA[lane][e]; tc[e] = c_T.xEncC[lane][e]; }
    const float* src = x + mv0 * 32;
    const int c = lane >> 3, qk = lane & 7;
#pragma unroll 4
    for (int j = 0; j < 32; j++) {
        float v = src[j * 32 + lane];
        float o1 = 0.f, o2 = 0.f;
#pragma unroll
        for (int e = 0; e < 4; e++) o1 += tc[e] * __shfl_sync(0xffffffffu, v, ta[e]);
#pragma unroll
        for (int e = 4; e < 8; e++) o2 += tc[e] * __shfl_sync(0xffffffffu, v, ta[e]);
        size_t mv = mv0 + j;
        size_t bs = mv >> 8, ii = mv & 255;
        g_A[(bs * 4 + c) * K2 + ii * 8 + qk] = __float2half_rn(o1 + o2);
    }
}

// ---------------- encode w: B[(o*8+r*2+pn)][(i*8+q*2+pk)] fp16 ----------------
__global__ void encode_w_kernel(const float* __restrict__ w) {
    const int lane = threadIdx.x & 31, warp = threadIdx.x >> 5;
    const int wg = blockIdx.x * 8 + warp;          // 0..2047
    const int o = wg >> 3, i0 = (wg & 7) * 32;
    int ta[2][8]; float tc[2][8];
#pragma unroll
    for (int p = 0; p < 2; p++)
#pragma unroll
        for (int e = 0; e < 8; e++) {
            ta[p][e] = c_T.wEncA[lane + 32 * p][e];
            tc[p][e] = c_T.wEncC[lane + 32 * p][e];
        }
#pragma unroll 2
    for (int j = 0; j < 32; j++) {
        int i = i0 + j;
        float v = w[((size_t)o * 256 + i) * 32 + lane];
#pragma unroll
        for (int p = 0; p < 2; p++) {
            int u = lane + 32 * p;
            float ov = 0.f;
#pragma unroll
            for (int e = 0; e < 8; e++)
                ov += tc[p][e] * __shfl_sync(0xffffffffu, v, ta[p][e]);
            g_B[(size_t)(o * 8 + (u >> 3)) * K2 + i * 8 + (u & 7)] = __float2half_rn(ov);
        }
    }
}

// ---------------- GEMM + fused decode/normalize ----------------
#define BM 128
#define BN 256
#define BK 64
#define STAGES 4
#define NT (K2 / BK)               // 32
#define A_BYTES (BM * 128)
#define B_BYTES (BN * 128)
#define STAGE_BYTES (A_BYTES + B_BYTES)          // 49152
#define SMEM_BYTES (STAGES * STAGE_BYTES)        // 196608 (epilogue needs 135168)
#define PITCH 264                                // 256 + 8: conflict-free epilogue

static __device__ __forceinline__ uint32_t smem_u32(const void* p) {
    return (uint32_t)__cvta_generic_to_shared(p);
}
static __device__ __forceinline__ void cp_async16(uint32_t s, const void* g) {
    asm volatile("cp.async.cg.shared.global [%0], [%1], 16;\n" :: "r"(s), "l"(g));
}

__global__ void __launch_bounds__(512, 1) gemm_hmma_kernel(float* __restrict__ out) {
    extern __shared__ char sm[];
    const uint32_t sbase = smem_u32(sm);

    const int tid  = threadIdx.x;
    const int lane = tid & 31;
    const int warp = tid >> 5;
    const int wm = (warp & 1) * 64;
    const int wn = (warp >> 1) * 32;
    const int bm = blockIdx.x * BM;
    const int bn = blockIdx.y * BN;

    const __half* A = g_A;
    const __half* B = g_B;

    float acc[4][4][4];
#pragma unroll
    for (int a = 0; a < 4; a++)
#pragma unroll
        for (int b = 0; b < 4; b++)
#pragma unroll
            for (int c = 0; c < 4; c++) acc[a][b][c] = 0.0f;

    auto load_stage = [&](int t) {
        const uint32_t st = sbase + (t % STAGES) * STAGE_BYTES;
        const int k0 = t * BK;
#pragma unroll
        for (int q = 0; q < 2; q++) {
            int c = tid + q * 512;
            int r = c >> 3, cc = c & 7;
            cp_async16(st + r * 128 + ((cc ^ (r & 7)) * 16),
                       A + (size_t)(bm + r) * K2 + k0 + cc * 8);
        }
#pragma unroll
        for (int q = 0; q < 4; q++) {
            int c = tid + q * 512;
            int r = c >> 3, cc = c & 7;
            cp_async16(st + A_BYTES + r * 128 + ((cc ^ (r & 7)) * 16),
                       B + (size_t)(bn + r) * K2 + k0 + cc * 8);
        }
        asm volatile("cp.async.commit_group;\n");
    };

    load_stage(0);
    load_stage(1);
    load_stage(2);

    const int aRow = wm + (lane & 15);
    const int aHi  = lane >> 4;
    const int aRx  = aRow & 7;
    const int bRow = wn + (lane & 7) + ((lane & 16) >> 1);
    const int bHi  = (lane >> 3) & 1;
    const int bRx  = bRow & 7;

    for (int t = 0; t < NT; t++) {
        if (t + 2 < NT)      asm volatile("cp.async.wait_group 2;\n");
        else if (t + 1 < NT) asm volatile("cp.async.wait_group 1;\n");
        else                 asm volatile("cp.async.wait_group 0;\n");
        __syncthreads();

        if (t + 3 < NT) load_stage(t + 3);

        const uint32_t st = sbase + (t % STAGES) * STAGE_BYTES;
        const uint32_t aB = st + aRow * 128;
        const uint32_t bB = st + A_BYTES + bRow * 128;

#pragma unroll
        for (int ks = 0; ks < 4; ks++) {
            uint32_t a[4][4];
#pragma unroll
            for (int mi = 0; mi < 4; mi++) {
                uint32_t addr = aB + mi * (16 * 128) + (((ks * 2 + aHi) ^ aRx) * 16);
                asm volatile("ldmatrix.sync.aligned.m8n8.x4.shared.b16 {%0,%1,%2,%3}, [%4];\n"
                             : "=r"(a[mi][0]), "=r"(a[mi][1]), "=r"(a[mi][2]), "=r"(a[mi][3])
                             : "r"(addr));
            }
            uint32_t b[4][2];
#pragma unroll
            for (int nb = 0; nb < 2; nb++) {
                uint32_t addr = bB + nb * (16 * 128) + (((ks * 2 + bHi) ^ bRx) * 16);
                asm volatile("ldmatrix.sync.aligned.m8n8.x4.shared.b16 {%0,%1,%2,%3}, [%4];\n"
                             : "=r"(b[2 * nb][0]), "=r"(b[2 * nb][1]),
                               "=r"(b[2 * nb + 1][0]), "=r"(b[2 * nb + 1][1])
                             : "r"(addr));
            }
#pragma unroll
            for (int mi = 0; mi < 4; mi++)
#pragma unroll
                for (int nj = 0; nj < 4; nj++) {
                    asm volatile(
                        "mma.sync.aligned.m16n8k16.row.col.f32.f16.f16.f32 "
                        "{%0,%1,%2,%3},{%4,%5,%6,%7},{%8,%9},{%0,%1,%2,%3};\n"
                        : "+f"(acc[mi][nj][0]), "+f"(acc[mi][nj][1]),
                          "+f"(acc[mi][nj][2]), "+f"(acc[mi][nj][3])
                        : "r"(a[mi][0]), "r"(a[mi][1]), "r"(a[mi][2]), "r"(a[mi][3]),
                          "r"(b[nj][0]), "r"(b[nj][1]));
                }
        }
    }

    // ---------------- epilogue: stage tile in smem ----------------
    __syncthreads();   // all warps done reading stage buffers
    float* smf = reinterpret_cast<float*>(sm);
#pragma unroll
    for (int mi = 0; mi < 4; mi++)
#pragma unroll
        for (int h = 0; h < 2; h++) {
            const int row = wm + mi * 16 + h * 8 + (lane >> 2);
            float* p = smf + (size_t)row * PITCH + wn + (lane & 3) * 2;
#pragma unroll
            for (int nj = 0; nj < 4; nj++)
                *reinterpret_cast<float2*>(p + nj * 8) =
                    make_float2(acc[mi][nj][2 * h], acc[mi][nj][2 * h + 1]);
        }
    __syncthreads();

    // ---------------- fused decode + normalize ----------------
    // Warp decodes 64 multivectors; lane = blade.
    int tu[4]; float tre[4], tim[4];
#pragma unroll
    for (int r = 0; r < 4; r++) {
        tu[r]  = c_T.decU[lane][r];
        tre[r] = c_T.decRe[lane][r];
        tim[r] = c_T.decIm[lane][r];
    }
    const int cc = lane >> 3, rp = lane & 7;
    const int bs0 = bm >> 2, o0 = bn >> 3;
#pragma unroll 2
    for (int j = 0; j < 64; j++) {
        const int mvloc = warp * 64 + j;
        const int bsl = mvloc >> 5, ol = mvloc & 31;
        float v = smf[(size_t)(bsl * 4 + cc) * PITCH + ol * 8 + rp];
        float xa = 0.f;
#pragma unroll
        for (int r = 0; r < 4; r++) {
            float vre = __shfl_sync(0xffffffffu, v, tu[r]);
            float vim = __shfl_sync(0xffffffffu, v, tu[r] + 1);
            xa += tre[r] * vre + tim[r] * vim;
        }
        float ss = xa * xa;
#pragma unroll
        for (int off = 16; off; off >>= 1) ss += __shfl_xor_sync(0xffffffffu, ss, off);
        out[((size_t)(bs0 + bsl) * 256 + (o0 + ol)) * 32 + lane] = xa * rsqrtf(ss + 1e-6f);
    }
}

// ---------------- launch ----------------
extern "C" void kernel_launch(void* const* d_in, const int* in_sizes, int n_in,
                              void* d_out, int out_size) {
    const float* x = (const float*)d_in[0];   // [2,1024,256,32] fp32
    const float* w = (const float*)d_in[1];   // [256,256,32]   fp32
    float* out = (float*)d_out;               // [2,1024,256,32] fp32

    encode_x_kernel<<<2048, 256>>>(x);
    encode_w_kernel<<<256, 256>>>(w);

    cudaFuncSetAttribute(gemm_hmma_kernel,
                         cudaFuncAttributeMaxDynamicSharedMemorySize, SMEM_BYTES);
    dim3 grid(M2 / BM, N2 / BN);   // (64, 8)
    gemm_hmma_kernel<<<grid, 512, SMEM_BYTES>>>(out);
}

// round 7
// speedup vs baseline: 3.7744x; 1.0577x over previous
#include <cuda_runtime.h>
#include <cuda_fp16.h>
#include <cstdint>

// Logical GEMM dims in the M4(C) matrix representation:
#define M2 8192    // (b*s)*4 matrix columns c
#define N2 2048    // o*8: (r, pn)
#define K2 2048    // i*8: (q, pk)

// Scratch (__device__ globals; allocation-free rules)
__device__ __align__(256) __half g_A[(size_t)M2 * K2];   // 32 MiB
__device__ __align__(256) __half g_B[(size_t)N2 * K2];   // 8 MiB

// ================= compile-time tables (Cl(4,1) ~= M4(C) rep) =================
struct Tables {
    int   xEncA[32][8]; float xEncC[32][8];
    int   wEncA[64][8]; float wEncC[64][8];
    int   decU[32][4];  float decRe[32][4]; float decIm[32][4];
};

constexpr float cfabs(float v) { return v < 0.f ? -v : v; }

constexpr void cmul4c(const float (&Ar)[4][4], const float (&Ai)[4][4],
                      const float (&Br)[4][4], const float (&Bi)[4][4],
                      float (&Cr)[4][4], float (&Ci)[4][4]) {
    for (int i = 0; i < 4; i++)
        for (int j = 0; j < 4; j++) {
            float re = 0.f, im = 0.f;
            for (int k = 0; k < 4; k++) {
                re += Ar[i][k] * Br[k][j] - Ai[i][k] * Bi[k][j];
                im += Ar[i][k] * Bi[k][j] + Ai[i][k] * Br[k][j];
            }
            Cr[i][j] = re; Ci[i][j] = im;
        }
}

constexpr Tables build_tables() {
    Tables T{};
    float Gre[5][4][4] = {}, Gim[5][4][4] = {};
    // gamma1 = [[0,s1],[s1,0]]
    Gre[0][0][3] = 1; Gre[0][1][2] = 1; Gre[0][2][1] = 1; Gre[0][3][0] = 1;
    // gamma2 = [[0,s2],[s2,0]], s2 = [[0,-i],[i,0]]
    Gim[1][0][3] = -1; Gim[1][1][2] = 1; Gim[1][2][1] = -1; Gim[1][3][0] = 1;
    // gamma3 = [[0,s3],[s3,0]], s3 = [[1,0],[0,-1]]
    Gre[2][0][2] = 1; Gre[2][1][3] = -1; Gre[2][2][0] = 1; Gre[2][3][1] = -1;
    // gamma4 = [[I,0],[0,-I]]
    Gre[3][0][0] = 1; Gre[3][1][1] = 1; Gre[3][2][2] = -1; Gre[3][3][3] = -1;
    // G5 = i * g1*g2*g3*g4  (squares to -1, anticommutes with g1..g4)
    {
        float Tr[4][4] = {}, Ti[4][4] = {}, Ur[4][4] = {}, Ui[4][4] = {};
        float Vr[4][4] = {}, Vi[4][4] = {};
        cmul4c(Gre[0], Gim[0], Gre[1], Gim[1], Tr, Ti);
        cmul4c(Tr, Ti, Gre[2], Gim[2], Ur, Ui);
        cmul4c(Ur, Ui, Gre[3], Gim[3], Vr, Vi);
        for (int i = 0; i < 4; i++)
            for (int j = 0; j < 4; j++) { Gre[4][i][j] = -Vi[i][j]; Gim[4][i][j] = Vr[i][j]; }
    }
    // R_a = ascending product of generators in bitmask a
    float Rre[32][4][4] = {}, Rim[32][4][4] = {};
    for (int a = 0; a < 32; a++) {
        float Rr[4][4] = {}, Ri[4][4] = {};
        Rr[0][0] = Rr[1][1] = Rr[2][2] = Rr[3][3] = 1.f;
        for (int b = 0; b < 5; b++)
            if ((a >> b) & 1) {
                float Tr[4][4] = {}, Ti[4][4] = {};
                cmul4c(Rr, Ri, Gre[b], Gim[b], Tr, Ti);
                for (int i = 0; i < 4; i++)
                    for (int j = 0; j < 4; j++) { Rr[i][j] = Tr[i][j]; Ri[i][j] = Ti[i][j]; }
            }
        for (int i = 0; i < 4; i++)
            for (int j = 0; j < 4; j++) { Rre[a][i][j] = Rr[i][j]; Rim[a][i][j] = Ri[i][j]; }
    }
    // X-encode: u = c*8 + q*2 + pk ; 8 blades with R[q][c] != 0
    for (int u = 0; u < 32; u++) {
        int c = u >> 3, q = (u >> 1) & 3, pk = u & 1, e = 0;
        for (int bl = 0; bl < 32; bl++) {
            float re = Rre[bl][q][c], im = Rim[bl][q][c];
            if (cfabs(re) + cfabs(im) > 0.5f) {
                T.xEncA[u][e] = bl;
                T.xEncC[u][e] = pk ? im : re;
                e++;
            }
        }
    }
    // W-encode: u = (r*2+pn)*8 + q*2 + pk
    for (int u = 0; u < 64; u++) {
        int rw = u >> 3, r = rw >> 1, pn = rw & 1;
        int qk = u & 7, q = qk >> 1, pk = qk & 1, e = 0;
        for (int bl = 0; bl < 32; bl++) {
            float re = Rre[bl][r][q], im = Rim[bl][r][q];
            if (cfabs(re) + cfabs(im) > 0.5f) {
                T.wEncA[u][e] = bl;
                T.wEncC[u][e] = (pn == 0) ? (pk == 0 ? re : -im)
                                          : (pk == 0 ? im : re);
                e++;
            }
        }
    }
    // decode: x_a = 1/4 * sum_r [ReR[r][c]*OUTre + ImR[r][c]*OUTim]
    for (int bl = 0; bl < 32; bl++)
        for (int r = 0; r < 4; r++)
            for (int c = 0; c < 4; c++) {
                float re = Rre[bl][r][c], im = Rim[bl][r][c];
                if (cfabs(re) + cfabs(im) > 0.5f) {
                    T.decU[bl][r]  = c * 8 + r * 2;
                    T.decRe[bl][r] = re * 0.25f;
                    T.decIm[bl][r] = im * 0.25f;
                }
            }
    return T;
}

__device__ const Tables c_T = build_tables();

// ---------------- merged encode: x -> g_A  and  w -> g_B ----------------
// blocks [0,2048): x-encode (8 warps, warp = 32 multivectors)
// blocks [2048,2304): w-encode
__global__ void encode_kernel(const float* __restrict__ x, const float* __restrict__ w) {
    const int lane = threadIdx.x & 31, warp = threadIdx.x >> 5;
    if (blockIdx.x < 2048) {
        const int wg = blockIdx.x * 8 + warp;          // 0..16383
        const size_t mv0 = (size_t)wg * 32;
        int ta[8]; float tc[8];
#pragma unroll
        for (int e = 0; e < 8; e++) { ta[e] = c_T.xEncA[lane][e]; tc[e] = c_T.xEncC[lane][e]; }
        const float* src = x + mv0 * 32;
        const int c = lane >> 3, qk = lane & 7;
        // bs is warp-constant: mv0 is a multiple of 32, block spans one 256-group
        const size_t bs = mv0 >> 8;
        const int ii0 = (int)(mv0 & 255);
        __half* dst = g_A + (bs * 4 + c) * K2 + (size_t)ii0 * 8 + qk;
#pragma unroll 2
        for (int j0 = 0; j0 < 32; j0 += 4) {
            float v0 = src[(j0 + 0) * 32 + lane];
            float v1 = src[(j0 + 1) * 32 + lane];
            float v2 = src[(j0 + 2) * 32 + lane];
            float v3 = src[(j0 + 3) * 32 + lane];
            float o0 = 0.f, o1 = 0.f, o2 = 0.f, o3 = 0.f;
#pragma unroll
            for (int e = 0; e < 8; e++) {
                o0 += tc[e] * __shfl_sync(0xffffffffu, v0, ta[e]);
                o1 += tc[e] * __shfl_sync(0xffffffffu, v1, ta[e]);
                o2 += tc[e] * __shfl_sync(0xffffffffu, v2, ta[e]);
                o3 += tc[e] * __shfl_sync(0xffffffffu, v3, ta[e]);
            }
            dst[(size_t)(j0 + 0) * 8] = __float2half_rn(o0);
            dst[(size_t)(j0 + 1) * 8] = __float2half_rn(o1);
            dst[(size_t)(j0 + 2) * 8] = __float2half_rn(o2);
            dst[(size_t)(j0 + 3) * 8] = __float2half_rn(o3);
        }
    } else {
        const int wg = (blockIdx.x - 2048) * 8 + warp; // 0..2047
        const int o = wg >> 3, i0 = (wg & 7) * 32;
        int ta[2][8]; float tc[2][8];
#pragma unroll
        for (int p = 0; p < 2; p++)
#pragma unroll
            for (int e = 0; e < 8; e++) {
                ta[p][e] = c_T.wEncA[lane + 32 * p][e];
                tc[p][e] = c_T.wEncC[lane + 32 * p][e];
            }
#pragma unroll 2
        for (int j = 0; j < 32; j++) {
            int i = i0 + j;
            float v = w[((size_t)o * 256 + i) * 32 + lane];
#pragma unroll
            for (int p = 0; p < 2; p++) {
                int u = lane + 32 * p;
                float ov = 0.f;
#pragma unroll
                for (int e = 0; e < 8; e++)
                    ov += tc[p][e] * __shfl_sync(0xffffffffu, v, ta[p][e]);
                g_B[(size_t)(o * 8 + (u >> 3)) * K2 + i * 8 + (u & 7)] = __float2half_rn(ov);
            }
        }
    }
}

// ---------------- GEMM + fused decode/normalize ----------------
#define BM 128
#define BN 256
#define BK 64
#define STAGES 4
#define NT (K2 / BK)               // 32
#define A_BYTES (BM * 128)
#define B_BYTES (BN * 128)
#define STAGE_BYTES (A_BYTES + B_BYTES)          // 49152
#define SMEM_BYTES (STAGES * STAGE_BYTES)        // 196608 (epilogue reuses 135168)
#define PITCH 264                                // 256 + 8: conflict-free epilogue

static __device__ __forceinline__ uint32_t smem_u32(const void* p) {
    return (uint32_t)__cvta_generic_to_shared(p);
}
static __device__ __forceinline__ void cp_async16(uint32_t s, const void* g) {
    asm volatile("cp.async.cg.shared.global [%0], [%1], 16;\n" :: "r"(s), "l"(g));
}

__global__ void __launch_bounds__(512, 1) gemm_hmma_kernel(float* __restrict__ out) {
    extern __shared__ char sm[];
    const uint32_t sbase = smem_u32(sm);

    const int tid  = threadIdx.x;
    const int lane = tid & 31;
    const int warp = tid >> 5;
    const int wm = (warp & 1) * 64;
    const int wn = (warp >> 1) * 32;
    const int bm = blockIdx.x * BM;
    const int bn = blockIdx.y * BN;

    const __half* A = g_A;
    const __half* B = g_B;

    float acc[4][4][4];
#pragma unroll
    for (int a = 0; a < 4; a++)
#pragma unroll
        for (int b = 0; b < 4; b++)
#pragma unroll
            for (int c = 0; c < 4; c++) acc[a][b][c] = 0.0f;

    auto load_stage = [&](int t) {
        const uint32_t st = sbase + (t % STAGES) * STAGE_BYTES;
        const int k0 = t * BK;
#pragma unroll
        for (int q = 0; q < 2; q++) {
            int c = tid + q * 512;
            int r = c >> 3, cc = c & 7;
            cp_async16(st + r * 128 + ((cc ^ (r & 7)) * 16),
                       A + (size_t)(bm + r) * K2 + k0 + cc * 8);
        }
#pragma unroll
        for (int q = 0; q < 4; q++) {
            int c = tid + q * 512;
            int r = c >> 3, cc = c & 7;
            cp_async16(st + A_BYTES + r * 128 + ((cc ^ (r & 7)) * 16),
                       B + (size_t)(bn + r) * K2 + k0 + cc * 8);
        }
        asm volatile("cp.async.commit_group;\n");
    };

    load_stage(0);
    load_stage(1);
    load_stage(2);

    const int aRow = wm + (lane & 15);
    const int aHi  = lane >> 4;
    const int aRx  = aRow & 7;
    const int bRow = wn + (lane & 7) + ((lane & 16) >> 1);
    const int bHi  = (lane >> 3) & 1;
    const int bRx  = bRow & 7;

    for (int t = 0; t < NT; t++) {
        if (t + 2 < NT)      asm volatile("cp.async.wait_group 2;\n");
        else if (t + 1 < NT) asm volatile("cp.async.wait_group 1;\n");
        else                 asm volatile("cp.async.wait_group 0;\n");
        __syncthreads();

        if (t + 3 < NT) load_stage(t + 3);

        const uint32_t st = sbase + (t % STAGES) * STAGE_BYTES;
        const uint32_t aB = st + aRow * 128;
        const uint32_t bB = st + A_BYTES + bRow * 128;

#pragma unroll
        for (int ks = 0; ks < 4; ks++) {
            uint32_t a[4][4];
#pragma unroll
            for (int mi = 0; mi < 4; mi++) {
                uint32_t addr = aB + mi * (16 * 128) + (((ks * 2 + aHi) ^ aRx) * 16);
                asm volatile("ldmatrix.sync.aligned.m8n8.x4.shared.b16 {%0,%1,%2,%3}, [%4];\n"
                             : "=r"(a[mi][0]), "=r"(a[mi][1]), "=r"(a[mi][2]), "=r"(a[mi][3])
                             : "r"(addr));
            }
            uint32_t b[4][2];
#pragma unroll
            for (int nb = 0; nb < 2; nb++) {
                uint32_t addr = bB + nb * (16 * 128) + (((ks * 2 + bHi) ^ bRx) * 16);
                asm volatile("ldmatrix.sync.aligned.m8n8.x4.shared.b16 {%0,%1,%2,%3}, [%4];\n"
                             : "=r"(b[2 * nb][0]), "=r"(b[2 * nb][1]),
                               "=r"(b[2 * nb + 1][0]), "=r"(b[2 * nb + 1][1])
                             : "r"(addr));
            }
#pragma unroll
            for (int mi = 0; mi < 4; mi++)
#pragma unroll
                for (int nj = 0; nj < 4; nj++) {
                    asm volatile(
                        "mma.sync.aligned.m16n8k16.row.col.f32.f16.f16.f32 "
                        "{%0,%1,%2,%3},{%4,%5,%6,%7},{%8,%9},{%0,%1,%2,%3};\n"
                        : "+f"(acc[mi][nj][0]), "+f"(acc[mi][nj][1]),
                          "+f"(acc[mi][nj][2]), "+f"(acc[mi][nj][3])
                        : "r"(a[mi][0]), "r"(a[mi][1]), "r"(a[mi][2]), "r"(a[mi][3]),
                          "r"(b[nj][0]), "r"(b[nj][1]));
                }
        }
    }

    // ---------------- epilogue: stage tile in smem ----------------
    __syncthreads();   // all warps done reading stage buffers
    float* smf = reinterpret_cast<float*>(sm);
#pragma unroll
    for (int mi = 0; mi < 4; mi++)
#pragma unroll
        for (int h = 0; h < 2; h++) {
            const int row = wm + mi * 16 + h * 8 + (lane >> 2);
            float* p = smf + (size_t)row * PITCH + wn + (lane & 3) * 2;
#pragma unroll
            for (int nj = 0; nj < 4; nj++)
                *reinterpret_cast<float2*>(p + nj * 8) =
                    make_float2(acc[mi][nj][2 * h], acc[mi][nj][2 * h + 1]);
        }
    __syncthreads();

    // ---------------- fused decode + normalize ----------------
    int tu[4]; float tre[4], tim[4];
#pragma unroll
    for (int r = 0; r < 4; r++) {
        tu[r]  = c_T.decU[lane][r];
        tre[r] = c_T.decRe[lane][r];
        tim[r] = c_T.decIm[lane][r];
    }
    const int cc = lane >> 3, rp = lane & 7;
    const int bs0 = bm >> 2, o0 = bn >> 3;
#pragma unroll 2
    for (int j = 0; j < 64; j++) {
        const int mvloc = warp * 64 + j;
        const int bsl = mvloc >> 5, ol = mvloc & 31;
        float v = smf[(size_t)(bsl * 4 + cc) * PITCH + ol * 8 + rp];
        float xa = 0.f;
#pragma unroll
        for (int r = 0; r < 4; r++) {
            float vre = __shfl_sync(0xffffffffu, v, tu[r]);
            float vim = __shfl_sync(0xffffffffu, v, tu[r] + 1);
            xa += tre[r] * vre + tim[r] * vim;
        }
        float ss = xa * xa;
#pragma unroll
        for (int off = 16; off; off >>= 1) ss += __shfl_xor_sync(0xffffffffu, ss, off);
        out[((size_t)(bs0 + bsl) * 256 + (o0 + ol)) * 32 + lane] = xa * rsqrtf(ss + 1e-6f);
    }
}

// ---------------- launch ----------------
extern "C" void kernel_launch(void* const* d_in, const int* in_sizes, int n_in,
                              void* d_out, int out_size) {
    const float* x = (const float*)d_in[0];   // [2,1024,256,32] fp32
    const float* w = (const float*)d_in[1];   // [256,256,32]   fp32
    float* out = (float*)d_out;               // [2,1024,256,32] fp32

    encode_kernel<<<2304, 256>>>(x, w);

    cudaFuncSetAttribute(gemm_hmma_kernel,
                         cudaFuncAttributeMaxDynamicSharedMemorySize, SMEM_BYTES);
    dim3 grid(M2 / BM, N2 / BN);   // (64, 8)
    gemm_hmma_kernel<<<grid, 512, SMEM_BYTES>>>(out);
}

// round 9
// speedup vs baseline: 4.7741x; 1.2648x over previous
#include <cuda_runtime.h>
#include <cuda_fp16.h>
#include <cstdint>

// Logical GEMM dims in the M4(C) matrix representation:
#define M2 8192    // (b*s)*4 matrix columns c
#define N2 2048    // o*8: (r, pn)
#define K2 2048    // i*8: (q, pk)

// Scratch (__device__ globals; allocation-free rules)
__device__ __align__(256) __half g_A[(size_t)M2 * K2];   // 32 MiB
__device__ __align__(256) __half g_B[(size_t)N2 * K2];   // 8 MiB

// ================= compile-time tables (Cl(4,1) ~= M4(C) rep) =================
struct Tables {
    int   xEncA[32][8]; float xEncC[32][8];
    int   wEncA[64][8]; float wEncC[64][8];
    int   decU[32][4];  float decRe[32][4]; float decIm[32][4];
};

constexpr float cfabs(float v) { return v < 0.f ? -v : v; }

constexpr void cmul4c(const float (&Ar)[4][4], const float (&Ai)[4][4],
                      const float (&Br)[4][4], const float (&Bi)[4][4],
                      float (&Cr)[4][4], float (&Ci)[4][4]) {
    for (int i = 0; i < 4; i++)
        for (int j = 0; j < 4; j++) {
            float re = 0.f, im = 0.f;
            for (int k = 0; k < 4; k++) {
                re += Ar[i][k] * Br[k][j] - Ai[i][k] * Bi[k][j];
                im += Ar[i][k] * Bi[k][j] + Ai[i][k] * Br[k][j];
            }
            Cr[i][j] = re; Ci[i][j] = im;
        }
}

constexpr Tables build_tables() {
    Tables T{};
    float Gre[5][4][4] = {}, Gim[5][4][4] = {};
    Gre[0][0][3] = 1; Gre[0][1][2] = 1; Gre[0][2][1] = 1; Gre[0][3][0] = 1;
    Gim[1][0][3] = -1; Gim[1][1][2] = 1; Gim[1][2][1] = -1; Gim[1][3][0] = 1;
    Gre[2][0][2] = 1; Gre[2][1][3] = -1; Gre[2][2][0] = 1; Gre[2][3][1] = -1;
    Gre[3][0][0] = 1; Gre[3][1][1] = 1; Gre[3][2][2] = -1; Gre[3][3][3] = -1;
    { // G5 = i * g1*g2*g3*g4
        float Tr[4][4] = {}, Ti[4][4] = {}, Ur[4][4] = {}, Ui[4][4] = {};
        float Vr[4][4] = {}, Vi[4][4] = {};
        cmul4c(Gre[0], Gim[0], Gre[1], Gim[1], Tr, Ti);
        cmul4c(Tr, Ti, Gre[2], Gim[2], Ur, Ui);
        cmul4c(Ur, Ui, Gre[3], Gim[3], Vr, Vi);
        for (int i = 0; i < 4; i++)
            for (int j = 0; j < 4; j++) { Gre[4][i][j] = -Vi[i][j]; Gim[4][i][j] = Vr[i][j]; }
    }
    float Rre[32][4][4] = {}, Rim[32][4][4] = {};
    for (int a = 0; a < 32; a++) {
        float Rr[4][4] = {}, Ri[4][4] = {};
        Rr[0][0] = Rr[1][1] = Rr[2][2] = Rr[3][3] = 1.f;
        for (int b = 0; b < 5; b++)
            if ((a >> b) & 1) {
                float Tr[4][4] = {}, Ti[4][4] = {};
                cmul4c(Rr, Ri, Gre[b], Gim[b], Tr, Ti);
                for (int i = 0; i < 4; i++)
                    for (int j = 0; j < 4; j++) { Rr[i][j] = Tr[i][j]; Ri[i][j] = Ti[i][j]; }
            }
        for (int i = 0; i < 4; i++)
            for (int j = 0; j < 4; j++) { Rre[a][i][j] = Rr[i][j]; Rim[a][i][j] = Ri[i][j]; }
    }
    for (int u = 0; u < 32; u++) {   // X-encode: u = c*8 + q*2 + pk
        int c = u >> 3, q = (u >> 1) & 3, pk = u & 1, e = 0;
        for (int bl = 0; bl < 32; bl++) {
            float re = Rre[bl][q][c], im = Rim[bl][q][c];
            if (cfabs(re) + cfabs(im) > 0.5f) {
                T.xEncA[u][e] = bl;
                T.xEncC[u][e] = pk ? im : re;
                e++;
            }
        }
    }
    for (int u = 0; u < 64; u++) {   // W-encode: u = (r*2+pn)*8 + q*2 + pk
        int rw = u >> 3, r = rw >> 1, pn = rw & 1;
        int qk = u & 7, q = qk >> 1, pk = qk & 1, e = 0;
        for (int bl = 0; bl < 32; bl++) {
            float re = Rre[bl][r][q], im = Rim[bl][r][q];
            if (cfabs(re) + cfabs(im) > 0.5f) {
                T.wEncA[u][e] = bl;
                T.wEncC[u][e] = (pn == 0) ? (pk == 0 ? re : -im)
                                          : (pk == 0 ? im : re);
                e++;
            }
        }
    }
    for (int bl = 0; bl < 32; bl++)  // decode
        for (int r = 0; r < 4; r++)
            for (int c = 0; c < 4; c++) {
                float re = Rre[bl][r][c], im = Rim[bl][r][c];
                if (cfabs(re) + cfabs(im) > 0.5f) {
                    T.decU[bl][r]  = c * 8 + r * 2;
                    T.decRe[bl][r] = re * 0.25f;
                    T.decIm[bl][r] = im * 0.25f;
                }
            }
    return T;
}

__device__ const Tables c_T = build_tables();  // runtime-indexed in decode

// ---- compile-time unrolled encode terms: coefficients become SASS immediates ----
// (static constexpr data members are used by value -> no host-variable odr-use)
template<int U, int E>
struct EX {
    static constexpr float C = build_tables().xEncC[U][E];
    static constexpr int   A = build_tables().xEncA[U][E];
    static __device__ __forceinline__ float f(const float (&x)[32]) {
        return C * x[A] + EX<U, E - 1>::f(x);
    }
};
template<int U> struct EX<U, -1> {
    static __device__ __forceinline__ float f(const float (&)[32]) { return 0.f; }
};
template<int C, int Q>
struct FX {
    static __device__ __forceinline__ void f(const float (&x)[32], __half* h) {
        h[Q] = __float2half_rn(EX<C * 8 + Q, 7>::f(x));
        FX<C, Q - 1>::f(x, h);
    }
};
template<int C> struct FX<C, -1> {
    static __device__ __forceinline__ void f(const float (&)[32], __half*) {}
};

template<int U, int E>
struct EW {
    static constexpr float C = build_tables().wEncC[U][E];
    static constexpr int   A = build_tables().wEncA[U][E];
    static __device__ __forceinline__ float f(const float (&x)[32]) {
        return C * x[A] + EW<U, E - 1>::f(x);
    }
};
template<int U> struct EW<U, -1> {
    static __device__ __forceinline__ float f(const float (&)[32]) { return 0.f; }
};
template<int RW, int Q>
struct FW {
    static __device__ __forceinline__ void f(const float (&x)[32], __half* h) {
        h[Q] = __float2half_rn(EW<RW * 8 + Q, 7>::f(x));
        FW<RW, Q - 1>::f(x, h);
    }
};
template<int RW> struct FW<RW, -1> {
    static __device__ __forceinline__ void f(const float (&)[32], __half*) {}
};

// ---------------- encode: one multivector per thread, all compile-time signs ----------------
// blocks [0,2048): x (524288 mvs).  blocks [2048,2304): w (65536 mvs).
__global__ void encode_kernel(const float4* __restrict__ x, const float4* __restrict__ w) {
    if (blockIdx.x < 2048) {
        const size_t mv = (size_t)blockIdx.x * 256 + threadIdx.x;
        float xr[32];
        const float4* src = x + mv * 8;
#pragma unroll
        for (int q = 0; q < 8; q++) {
            float4 v = src[q];
            xr[4 * q] = v.x; xr[4 * q + 1] = v.y; xr[4 * q + 2] = v.z; xr[4 * q + 3] = v.w;
        }
        const size_t bs = mv >> 8;
        const int ii = (int)(mv & 255);
        __align__(16) __half h0[8], h1[8], h2[8], h3[8];
        FX<0, 7>::f(xr, h0); FX<1, 7>::f(xr, h1);
        FX<2, 7>::f(xr, h2); FX<3, 7>::f(xr, h3);
        *reinterpret_cast<uint4*>(g_A + (bs * 4 + 0) * K2 + ii * 8) = *reinterpret_cast<uint4*>(h0);
        *reinterpret_cast<uint4*>(g_A + (bs * 4 + 1) * K2 + ii * 8) = *reinterpret_cast<uint4*>(h1);
        *reinterpret_cast<uint4*>(g_A + (bs * 4 + 2) * K2 + ii * 8) = *reinterpret_cast<uint4*>(h2);
        *reinterpret_cast<uint4*>(g_A + (bs * 4 + 3) * K2 + ii * 8) = *reinterpret_cast<uint4*>(h3);
    } else {
        const int mv = (blockIdx.x - 2048) * 256 + threadIdx.x;   // (o,i)
        const int o = mv >> 8, i = mv & 255;
        float xr[32];
        const float4* src = w + (size_t)mv * 8;
#pragma unroll
        for (int q = 0; q < 8; q++) {
            float4 v = src[q];
            xr[4 * q] = v.x; xr[4 * q + 1] = v.y; xr[4 * q + 2] = v.z; xr[4 * q + 3] = v.w;
        }
        __align__(16) __half h[8][8];
        FW<0, 7>::f(xr, h[0]); FW<1, 7>::f(xr, h[1]);
        FW<2, 7>::f(xr, h[2]); FW<3, 7>::f(xr, h[3]);
        FW<4, 7>::f(xr, h[4]); FW<5, 7>::f(xr, h[5]);
        FW<6, 7>::f(xr, h[6]); FW<7, 7>::f(xr, h[7]);
#pragma unroll
        for (int rw = 0; rw < 8; rw++)
            *reinterpret_cast<uint4*>(g_B + (size_t)(o * 8 + rw) * K2 + i * 8) =
                *reinterpret_cast<uint4*>(h[rw]);
    }
}

// ---------------- GEMM + fused decode/normalize ----------------
// CTA 128x128, 256 threads (8 warps: 2M x 4N, warp 64x32), 3 stages -> 2 CTAs/SM.
#define BM 128
#define BN 128
#define BK 64
#define STAGES 3
#define NT (K2 / BK)               // 32
#define A_BYTES (BM * 128)         // 16384
#define B_BYTES (BN * 128)         // 16384
#define STAGE_BYTES (A_BYTES + B_BYTES)          // 32768
#define SMEM_BYTES (STAGES * STAGE_BYTES)        // 98304
#define PITCH 136                                // 128 + 8: conflict-free epilogue

static __device__ __forceinline__ uint32_t smem_u32(const void* p) {
    return (uint32_t)__cvta_generic_to_shared(p);
}
static __device__ __forceinline__ void cp_async16(uint32_t s, const void* g) {
    asm volatile("cp.async.cg.shared.global [%0], [%1], 16;\n" :: "r"(s), "l"(g));
}

__global__ void __launch_bounds__(256, 2) gemm_hmma_kernel(float* __restrict__ out) {
    extern __shared__ char sm[];
    const uint32_t sbase = smem_u32(sm);

    const int tid  = threadIdx.x;
    const int lane = tid & 31;
    const int warp = tid >> 5;
    const int wm = (warp & 1) * 64;      // 2 warps along M
    const int wn = (warp >> 1) * 32;     // 4 warps along N
    const int bm = blockIdx.x * BM;
    const int bn = blockIdx.y * BN;

    const __half* A = g_A;
    const __half* B = g_B;

    float acc[4][4][4];
#pragma unroll
    for (int a = 0; a < 4; a++)
#pragma unroll
        for (int b = 0; b < 4; b++)
#pragma unroll
            for (int c = 0; c < 4; c++) acc[a][b][c] = 0.0f;

    auto load_stage = [&](int t) {
        const uint32_t st = sbase + (t % STAGES) * STAGE_BYTES;
        const int k0 = t * BK;
#pragma unroll
        for (int q = 0; q < 4; q++) {    // A: 1024 chunks / 256 thr
            int c = tid + q * 256;
            int r = c >> 3, cc = c & 7;
            cp_async16(st + r * 128 + ((cc ^ (r & 7)) * 16),
                       A + (size_t)(bm + r) * K2 + k0 + cc * 8);
        }
#pragma unroll
        for (int q = 0; q < 4; q++) {    // B: 1024 chunks
            int c = tid + q * 256;
            int r = c >> 3, cc = c & 7;
            cp_async16(st + A_BYTES + r * 128 + ((cc ^ (r & 7)) * 16),
                       B + (size_t)(bn + r) * K2 + k0 + cc * 8);
        }
        asm volatile("cp.async.commit_group;\n");
    };

    load_stage(0);
    load_stage(1);

    const int aRow = wm + (lane & 15);
    const int aHi  = lane >> 4;
    const int aRx  = aRow & 7;
    const int bRow = wn + (lane & 7) + ((lane & 16) >> 1);
    const int bHi  = (lane >> 3) & 1;
    const int bRx  = bRow & 7;

    for (int t = 0; t < NT; t++) {
        if (t + 1 < NT) asm volatile("cp.async.wait_group 1;\n");
        else            asm volatile("cp.async.wait_group 0;\n");
        __syncthreads();

        if (t + 2 < NT) load_stage(t + 2);

        const uint32_t st = sbase + (t % STAGES) * STAGE_BYTES;
        const uint32_t aB = st + aRow * 128;
        const uint32_t bB = st + A_BYTES + bRow * 128;

#pragma unroll
        for (int ks = 0; ks < 4; ks++) {
            uint32_t a[4][4];
#pragma unroll
            for (int mi = 0; mi < 4; mi++) {
                uint32_t addr = aB + mi * (16 * 128) + (((ks * 2 + aHi) ^ aRx) * 16);
                asm volatile("ldmatrix.sync.aligned.m8n8.x4.shared.b16 {%0,%1,%2,%3}, [%4];\n"
                             : "=r"(a[mi][0]), "=r"(a[mi][1]), "=r"(a[mi][2]), "=r"(a[mi][3])
                             : "r"(addr));
            }
            uint32_t b[4][2];
#pragma unroll
            for (int nb = 0; nb < 2; nb++) {
                uint32_t addr = bB + nb * (16 * 128) + (((ks * 2 + bHi) ^ bRx) * 16);
                asm volatile("ldmatrix.sync.aligned.m8n8.x4.shared.b16 {%0,%1,%2,%3}, [%4];\n"
                             : "=r"(b[2 * nb][0]), "=r"(b[2 * nb][1]),
                               "=r"(b[2 * nb + 1][0]), "=r"(b[2 * nb + 1][1])
                             : "r"(addr));
            }
#pragma unroll
            for (int mi = 0; mi < 4; mi++)
#pragma unroll
                for (int nj = 0; nj < 4; nj++) {
                    asm volatile(
                        "mma.sync.aligned.m16n8k16.row.col.f32.f16.f16.f32 "
                        "{%0,%1,%2,%3},{%4,%5,%6,%7},{%8,%9},{%0,%1,%2,%3};\n"
                        : "+f"(acc[mi][nj][0]), "+f"(acc[mi][nj][1]),
                          "+f"(acc[mi][nj][2]), "+f"(acc[mi][nj][3])
                        : "r"(a[mi][0]), "r"(a[mi][1]), "r"(a[mi][2]), "r"(a[mi][3]),
                          "r"(b[nj][0]), "r"(b[nj][1]));
                }
        }
    }

    // ---------------- epilogue: stage tile in smem ----------------
    __syncthreads();
    float* smf = reinterpret_cast<float*>(sm);
#pragma unroll
    for (int mi = 0; mi < 4; mi++)
#pragma unroll
        for (int h = 0; h < 2; h++) {
            const int row = wm + mi * 16 + h * 8 + (lane >> 2);
            float* p = smf + (size_t)row * PITCH + wn + (lane & 3) * 2;
#pragma unroll
            for (int nj = 0; nj < 4; nj++)
                *reinterpret_cast<float2*>(p + nj * 8) =
                    make_float2(acc[mi][nj][2 * h], acc[mi][nj][2 * h + 1]);
        }
    __syncthreads();

    // ---------------- fused decode + normalize (512 mvs, 64 per warp) ----------------
    int tu[4]; float tre[4], tim[4];
#pragma unroll
    for (int r = 0; r < 4; r++) {
        tu[r]  = c_T.decU[lane][r];
        tre[r] = c_T.decRe[lane][r];
        tim[r] = c_T.decIm[lane][r];
    }
    const int cc = lane >> 3, rp = lane & 7;
    const int bs0 = bm >> 2, o0 = bn >> 3;
#pragma unroll 2
    for (int j = 0; j < 64; j++) {
        const int mvloc = warp * 64 + j;
        const int bsl = mvloc >> 4, ol = mvloc & 15;
        float v = smf[(size_t)(bsl * 4 + cc) * PITCH + ol * 8 + rp];
        float xa = 0.f;
#pragma unroll
        for (int r = 0; r < 4; r++) {
            float vre = __shfl_sync(0xffffffffu, v, tu[r]);
            float vim = __shfl_sync(0xffffffffu, v, tu[r] + 1);
            xa += tre[r] * vre + tim[r] * vim;
        }
        float ss = xa * xa;
#pragma unroll
        for (int off = 16; off; off >>= 1) ss += __shfl_xor_sync(0xffffffffu, ss, off);
        out[((size_t)(bs0 + bsl) * 256 + (o0 + ol)) * 32 + lane] = xa * rsqrtf(ss + 1e-6f);
    }
}

// ---------------- launch ----------------
extern "C" void kernel_launch(void* const* d_in, const int* in_sizes, int n_in,
                              void* d_out, int out_size) {
    const float* x = (const float*)d_in[0];   // [2,1024,256,32] fp32
    const float* w = (const float*)d_in[1];   // [256,256,32]   fp32
    float* out = (float*)d_out;               // [2,1024,256,32] fp32

    encode_kernel<<<2304, 256>>>((const float4*)x, (const float4*)w);

    cudaFuncSetAttribute(gemm_hmma_kernel,
                         cudaFuncAttributeMaxDynamicSharedMemorySize, SMEM_BYTES);
    dim3 grid(M2 / BM, N2 / BN);   // (64, 16)
    gemm_hmma_kernel<<<grid, 256, SMEM_BYTES>>>(out);
}